// round 11
// baseline (speedup 1.0000x reference)
#include <cuda_runtime.h>
#include <cuda_bf16.h>
#include <mma.h>

using namespace nvcuda;

// ---------------- problem constants (fixed for this problem) ----------------
#define NN   96000      // nodes
#define EE   600000     // edges
#define HH   4          // heads
#define FFd  32         // features per head
#define HFd  128        // H*F
#define FIN  128        // input features
#define EDd  64         // edge feature dim
#define HID  256        // instruction hidden
#define BB   64         // batch
#define MLEc 1500       // max_local_entity
#define TWO_N (2*NN)
#define SBS  1024
#define SNB  ((TWO_N + SBS - 1) / SBS)   // 188

// ---------------- device scratch (static: no runtime allocation) -----------
__device__ float g_proj [(size_t)NN * HFd];   // x @ W_proj          49 MB
__device__ float g_skipb[(size_t)NN * HFd];   // x @ W_skip (bias added in k6)
__device__ float g_ssrc [NN * HH];
__device__ float g_strg [NN * HH];
__device__ float g_p    [(size_t)EE * HH];    // exp(leaky(score))   9.6 MB
__device__ int   g_deg  [TWO_N];
__device__ int   g_offs [TWO_N];
__device__ int   g_cur  [TWO_N];
__device__ int   g_bsum [SNB];
__device__ int   g_bscan[SNB];
__device__ int2  g_adj  [2 * EE];             // (neighbor, edge-id) packed
__device__ float g_Msrc [BB * HH * FIN];
__device__ float g_Mtrg [BB * HH * FIN];
__device__ float g_Medge[BB * HH * EDd];
// edge bucketing by batch id
__device__ int   g_bcnt [BB];
__device__ int   g_boff [BB + 1];
__device__ int   g_bcur [BB];
__device__ int   g_perm [EE];
// bf16-split operands for tensor-core GEMM
__device__ __nv_bfloat16 g_xh[(size_t)NN * FIN];
__device__ __nv_bfloat16 g_xl[(size_t)NN * FIN];
__device__ __nv_bfloat16 g_wh[FIN * 256];     // [Wproj | Wskip] hi
__device__ __nv_bfloat16 g_wl[FIN * 256];     // [Wproj | Wskip] lo

// ---------------- K0: zero counters -----------------------------------------
__global__ void k0_zero() {
    int i = blockIdx.x * blockDim.x + threadIdx.x;
    if (i < TWO_N) g_deg[i] = 0;
    if (i < BB)    g_bcnt[i] = 0;
}

// ---------------- K1: instruction bridges -> folded score matrices ----------
__global__ void k1_precompute(const float* __restrict__ ins,
                              const float* __restrict__ Wsrc, const float* __restrict__ bsrc,
                              const float* __restrict__ Wtrg, const float* __restrict__ btrg,
                              const float* __restrict__ Wei,  const float* __restrict__ bei,
                              const float* __restrict__ asrc, const float* __restrict__ atrg,
                              const float* __restrict__ aedg,
                              const float* __restrict__ Wproj, const float* __restrict__ Wedge)
{
    __shared__ float csrc[HFd], ctrg[HFd], cedg[HFd];
    int b = blockIdx.x;
    int j = threadIdx.x;                 // 128 threads
    const float* ib = ins + b * HID;
    float s1 = bsrc[j], s2 = btrg[j], s3 = bei[j];
    for (int k = 0; k < HID; ++k) {
        float iv = ib[k];
        s1 += iv * Wsrc[k * HFd + j];
        s2 += iv * Wtrg[k * HFd + j];
        s3 += iv * Wei [k * HFd + j];
    }
    csrc[j] = s1 * asrc[j];
    ctrg[j] = s2 * atrg[j];
    cedg[j] = s3 * aedg[j];
    __syncthreads();

    int d = j;
    for (int h = 0; h < HH; ++h) {
        float m1 = 0.f, m2 = 0.f;
        for (int f = 0; f < FFd; ++f) {
            float wp = Wproj[d * HFd + h * FFd + f];
            m1 += wp * csrc[h * FFd + f];
            m2 += wp * ctrg[h * FFd + f];
        }
        g_Msrc[b * HH * FIN + h * FIN + d] = m1;
        g_Mtrg[b * HH * FIN + h * FIN + d] = m2;
        if (d < EDd) {
            float m3 = 0.f;
            for (int f = 0; f < FFd; ++f)
                m3 += Wedge[d * HFd + h * FFd + f] * cedg[h * FFd + f];
            g_Medge[b * HH * EDd + h * EDd + d] = m3;
        }
    }
}

// ---------------- K2S: node scores + bf16-split conversion of x --------------
__global__ void __launch_bounds__(256) k2s_scores(const float* __restrict__ x) {
    __shared__ float xs[32][129];
    int t = threadIdx.x;
    int n0 = blockIdx.x * 32;
    for (int i = 0; i < 16; ++i) {
        int idx = i * 256 + t;
        xs[idx >> 7][idx & 127] = x[(size_t)(n0 + (idx >> 7)) * FIN + (idx & 127)];
    }
    __syncthreads();

    // bf16 hi/lo conversion (x staged once, reused for scores)
    for (int i = 0; i < 16; ++i) {
        int idx = i * 256 + t;
        float v = xs[idx >> 7][idx & 127];
        __nv_bfloat16 hg = __float2bfloat16_rn(v);
        g_xh[(size_t)n0 * FIN + idx] = hg;
        g_xl[(size_t)n0 * FIN + idx] = __float2bfloat16_rn(v - __bfloat162float(hg));
    }

    int node = t & 31;
    int q = t >> 5;                 // warp-uniform
    int h = q & 3;
    int n = n0 + node;
    int b = n / MLEc;
    const float* Mv = ((q < 4) ? g_Msrc : g_Mtrg) + b * HH * FIN + h * FIN;
    float s = 0.f;
    for (int d = 0; d < FIN; ++d) s += xs[node][d] * Mv[d];
    if (q < 4) g_ssrc[n * 4 + h] = s;
    else       g_strg[n * 4 + h] = s;
}

// ---------------- KC: bf16-split conversion of [Wproj|Wskip] -----------------
__global__ void kc_convw(const float* __restrict__ Wp, const float* __restrict__ Ws) {
    int idx = blockIdx.x * 256 + threadIdx.x;   // 0 .. 128*256-1
    if (idx >= FIN * 256) return;
    int r = idx >> 8, c = idx & 255;
    float v = (c < HFd) ? Wp[r * HFd + c] : Ws[r * HFd + (c - HFd)];
    __nv_bfloat16 h = __float2bfloat16_rn(v);
    g_wh[idx] = h;
    g_wl[idx] = __float2bfloat16_rn(v - __bfloat162float(h));
}

// ---------------- K2: tensor-core GEMM (bf16 split, fp32 acc) ----------------
// C[96000 x 256] = x[96000 x 128] @ [Wproj|Wskip][128 x 256]
__global__ void __launch_bounds__(256) k2_mma() {
    __shared__ __nv_bfloat16 Bh[FIN][72];
    __shared__ __nv_bfloat16 Bl[FIN][72];
    int t = threadIdx.x;
    int n0 = blockIdx.x * 64;
    int c0 = blockIdx.y * 64;

    for (int i = t; i < FIN * 64; i += 256) {
        int r = i >> 6, c = i & 63;
        Bh[r][c] = g_wh[r * 256 + c0 + c];
        Bl[r][c] = g_wl[r * 256 + c0 + c];
    }
    __syncthreads();

    int wid = t >> 5;
    int wr = wid >> 1;              // row tile 0..3
    int wcb = (wid & 1) * 2;        // col-tile base 0 or 2

    wmma::fragment<wmma::accumulator, 16, 16, 16, float> acc[2];
    wmma::fill_fragment(acc[0], 0.0f);
    wmma::fill_fragment(acc[1], 0.0f);

    const __nv_bfloat16* arow_h = g_xh + (size_t)(n0 + wr * 16) * FIN;
    const __nv_bfloat16* arow_l = g_xl + (size_t)(n0 + wr * 16) * FIN;

#pragma unroll
    for (int k = 0; k < FIN / 16; ++k) {
        wmma::fragment<wmma::matrix_a, 16, 16, 16, __nv_bfloat16, wmma::row_major> ah, al;
        wmma::load_matrix_sync(ah, arow_h + k * 16, FIN);
        wmma::load_matrix_sync(al, arow_l + k * 16, FIN);
#pragma unroll
        for (int f = 0; f < 2; ++f) {
            wmma::fragment<wmma::matrix_b, 16, 16, 16, __nv_bfloat16, wmma::row_major> bh, bl;
            wmma::load_matrix_sync(bh, &Bh[k * 16][(wcb + f) * 16], 72);
            wmma::load_matrix_sync(bl, &Bl[k * 16][(wcb + f) * 16], 72);
            wmma::mma_sync(acc[f], ah, bh, acc[f]);
            wmma::mma_sync(acc[f], ah, bl, acc[f]);
            wmma::mma_sync(acc[f], al, bh, acc[f]);
        }
    }

    float* dstbase = (c0 < HFd) ? g_proj : g_skipb;
    int cbase = (c0 < HFd) ? c0 : (c0 - HFd);
#pragma unroll
    for (int f = 0; f < 2; ++f) {
        int cg = cbase + (wcb + f) * 16;
        wmma::store_matrix_sync(dstbase + (size_t)(n0 + wr * 16) * HFd + cg,
                                acc[f], HFd, wmma::mem_row_major);
    }
}

// ---------------- KB: bucket edges by batch id -------------------------------
__global__ void __launch_bounds__(256) kb_hist(const int* __restrict__ bids) {
    __shared__ int h[BB];
    int t = threadIdx.x;
    if (t < BB) h[t] = 0;
    __syncthreads();
    int base = blockIdx.x * 1024;
#pragma unroll
    for (int j = 0; j < 4; ++j) {
        int e = base + j * 256 + t;
        if (e < EE) atomicAdd(&h[bids[e]], 1);
    }
    __syncthreads();
    if (t < BB && h[t]) atomicAdd(&g_bcnt[t], h[t]);
}

__global__ void kb_scan() {
    if (threadIdx.x == 0) {
        int s = 0;
        for (int b = 0; b < BB; ++b) {
            g_boff[b] = s; g_bcur[b] = s; s += g_bcnt[b];
        }
        g_boff[BB] = s;
    }
}

__global__ void __launch_bounds__(256) kb_fill(const int* __restrict__ bids) {
    __shared__ int h[BB], base[BB];
    int t = threadIdx.x;
    if (t < BB) h[t] = 0;
    __syncthreads();
    int e0 = blockIdx.x * 1024;
    int eb[4], rk[4];
#pragma unroll
    for (int j = 0; j < 4; ++j) {
        int e = e0 + j * 256 + t;
        if (e < EE) { eb[j] = bids[e]; rk[j] = atomicAdd(&h[eb[j]], 1); }
        else eb[j] = -1;
    }
    __syncthreads();
    if (t < BB && h[t]) base[t] = atomicAdd(&g_bcur[t], h[t]);
    __syncthreads();
#pragma unroll
    for (int j = 0; j < 4; ++j) {
        if (eb[j] >= 0) g_perm[base[eb[j]] + rk[j]] = e0 + j * 256 + t;
    }
}

// ---------------- K3: edge scores (batch-grouped) + exp + degree histogram ---
__global__ void __launch_bounds__(256) k3_edge(const float* __restrict__ edges,
                                               const int* __restrict__ ei)
{
    __shared__ float Me[HH * EDd];      // 1 KB
    int b = blockIdx.y;
    int t = threadIdx.x;
    Me[t] = g_Medge[b * HH * EDd + t];
    __syncthreads();

    int start = g_boff[b], end = g_boff[b + 1];
    const float4* Me4 = (const float4*)Me;

    for (int pos = start + blockIdx.x * 256 + t; pos < end; pos += gridDim.x * 256) {
        int e = g_perm[pos];
        const float4* er = (const float4*)(edges + (size_t)e * EDd);
        float a0 = 0.f, a1 = 0.f, a2 = 0.f, a3 = 0.f;
#pragma unroll
        for (int i = 0; i < 16; ++i) {
            float4 v  = er[i];
            float4 m0 = Me4[i];
            float4 m1 = Me4[16 + i];
            float4 m2 = Me4[32 + i];
            float4 m3 = Me4[48 + i];
            a0 += v.x * m0.x + v.y * m0.y + v.z * m0.z + v.w * m0.w;
            a1 += v.x * m1.x + v.y * m1.y + v.z * m1.z + v.w * m1.w;
            a2 += v.x * m2.x + v.y * m2.y + v.z * m2.z + v.w * m2.w;
            a3 += v.x * m3.x + v.y * m3.y + v.z * m3.z + v.w * m3.w;
        }
        int sv = ei[e], tv = ei[EE + e];
        float4 ss = *(const float4*)&g_ssrc[sv * 4];
        float4 st = *(const float4*)&g_strg[tv * 4];
        float s0 = a0 + ss.x + st.x;
        float s1 = a1 + ss.y + st.y;
        float s2 = a2 + ss.z + st.z;
        float s3 = a3 + ss.w + st.w;
        s0 = (s0 > 0.f) ? s0 : 0.2f * s0;
        s1 = (s1 > 0.f) ? s1 : 0.2f * s1;
        s2 = (s2 > 0.f) ? s2 : 0.2f * s2;
        s3 = (s3 > 0.f) ? s3 : 0.2f * s3;
        float4 p = make_float4(__expf(s0), __expf(s1), __expf(s2), __expf(s3));
        *(float4*)&g_p[(size_t)e * 4] = p;
        atomicAdd(&g_deg[sv], 1);
        atomicAdd(&g_deg[NN + tv], 1);
    }
}

// ---------------- K4: exclusive scan of degrees -> CSR offsets ---------------
__global__ void __launch_bounds__(SBS) k4a_scan() {
    __shared__ int sh[SBS];
    int t = threadIdx.x;
    int i = blockIdx.x * SBS + t;
    int v = (i < TWO_N) ? g_deg[i] : 0;
    sh[t] = v;
    __syncthreads();
    for (int off = 1; off < SBS; off <<= 1) {
        int tmp = (t >= off) ? sh[t - off] : 0;
        __syncthreads();
        if (t >= off) sh[t] += tmp;
        __syncthreads();
    }
    if (i < TWO_N) g_offs[i] = sh[t] - v;
    if (t == SBS - 1) g_bsum[blockIdx.x] = sh[t];
}

__global__ void k4b_bscan() {
    if (threadIdx.x == 0) {
        int s = 0;
        for (int i = 0; i < SNB; ++i) { g_bscan[i] = s; s += g_bsum[i]; }
    }
}

__global__ void __launch_bounds__(SBS) k4c_add() {
    int i = blockIdx.x * SBS + threadIdx.x;
    if (i < TWO_N) {
        int o = g_offs[i] + g_bscan[blockIdx.x];
        g_offs[i] = o;
        g_cur[i]  = o;
    }
}

// ---------------- K5: fill CSR (both directions, int2 packed) ----------------
__global__ void k5_fill(const int* __restrict__ ei) {
    int e = blockIdx.x * blockDim.x + threadIdx.x;
    if (e >= EE) return;
    int s = ei[e], t = ei[EE + e];
    int p1 = atomicAdd(&g_cur[s], 1);
    g_adj[p1] = make_int2(t, e);
    int p2 = atomicAdd(&g_cur[NN + t], 1);
    g_adj[p2] = make_int2(s, e);
}

// ---------------- K6: gather-aggregate + fused LN (2 warps per node) ---------
// block = 256 threads = 8 warps = 4 nodes; warp pair (dir 0/1) per node.
__global__ void __launch_bounds__(256) k6_agg(const float* __restrict__ bias,
                                              const float* __restrict__ gamma,
                                              const float* __restrict__ beta,
                                              float* __restrict__ out)
{
    __shared__ float ssum[8], ssq[8];
    int t = threadIdx.x;
    int node = (blockIdx.x * 256 + t) >> 6;      // NN*64 threads, exact grid
    int dir  = (t >> 5) & 1;                     // 0: src branch, 1: trg branch
    int l = t & 31;
    int h = l >> 3;
    int w_id = t >> 5;

    int base = dir ? (NN + node) : node;
    int st = g_offs[base], cnt = g_deg[base];

    float4 a = make_float4(0.f, 0.f, 0.f, 0.f);
    float d = 0.f;
    int2 ne = (cnt > 0) ? g_adj[st] : make_int2(0, 0);
    for (int i = 0; i < cnt; ++i) {
        int2 cur = ne;
        if (i + 1 < cnt) ne = g_adj[st + i + 1];   // prefetch next pair
        float w = g_p[(size_t)cur.y * 4 + h];
        float4 pv = *(const float4*)&g_proj[(size_t)cur.x * HFd + l * 4];
        a.x += pv.x * w; a.y += pv.y * w; a.z += pv.z * w; a.w += pv.w * w;
        d += w;
    }

    float4 sk = *(const float4*)&g_skipb[(size_t)node * HFd + l * 4];
    float4 bi = *(const float4*)&bias[l * 4];
    float inv = (d > 0.f) ? 1.f / d : 0.f;
    float4 v = make_float4(a.x * inv + sk.x + bi.x, a.y * inv + sk.y + bi.y,
                           a.z * inv + sk.z + bi.z, a.w * inv + sk.w + bi.w);

    float sum = v.x + v.y + v.z + v.w;
    float sq  = v.x * v.x + v.y * v.y + v.z * v.z + v.w * v.w;
#pragma unroll
    for (int off = 16; off > 0; off >>= 1) {
        sum += __shfl_xor_sync(0xffffffffu, sum, off);
        sq  += __shfl_xor_sync(0xffffffffu, sq,  off);
    }
    if (l == 0) { ssum[w_id] = sum; ssq[w_id] = sq; }
    __syncthreads();
    int peer = w_id ^ 1;
    float tot  = ssum[w_id] + ssum[peer];
    float tots = ssq[w_id]  + ssq[peer];
    float mu  = tot * (1.f / 256.f);
    float var = tots * (1.f / 256.f) - mu * mu;
    float rs  = rsqrtf(var + 1e-5f);

    int go = dir * HFd + l * 4;
    float4 g0 = *(const float4*)&gamma[go];
    float4 b0 = *(const float4*)&beta[go];
    float4 o = make_float4((v.x - mu) * rs * g0.x + b0.x,
                           (v.y - mu) * rs * g0.y + b0.y,
                           (v.z - mu) * rs * g0.z + b0.z,
                           (v.w - mu) * rs * g0.w + b0.w);
    *(float4*)&out[(size_t)node * 256 + go] = o;
}

// ---------------- launch ----------------------------------------------------
extern "C" void kernel_launch(void* const* d_in, const int* in_sizes, int n_in,
                              void* d_out, int out_size)
{
    int o = 0;
    if (n_in >= 21 && in_sizes[5] <= 2) o = 1;

    const float* x     = (const float*)d_in[0];
    const int*   ei    = (const int*)  d_in[1];
    const float* edges = (const float*)d_in[2];
    const float* ins   = (const float*)d_in[3];
    const int*   bids  = (const int*)  d_in[4];
    const float* Wproj = (const float*)d_in[5 + o];
    const float* Wedge = (const float*)d_in[6 + o];
    const float* Wsrc  = (const float*)d_in[7 + o];
    const float* bsrc  = (const float*)d_in[8 + o];
    const float* Wtrg  = (const float*)d_in[9 + o];
    const float* btrg  = (const float*)d_in[10 + o];
    const float* Wei   = (const float*)d_in[11 + o];
    const float* bei   = (const float*)d_in[12 + o];
    const float* asrc  = (const float*)d_in[13 + o];
    const float* atrg  = (const float*)d_in[14 + o];
    const float* aedg  = (const float*)d_in[15 + o];
    const float* bias  = (const float*)d_in[16 + o];
    const float* Wskip = (const float*)d_in[17 + o];
    const float* gamma = (const float*)d_in[18 + o];
    const float* beta  = (const float*)d_in[19 + o];
    float* out = (float*)d_out;

    // launch index 3 == profiled kernel -> k2_mma this round
    k1_precompute<<<BB, 128>>>(ins, Wsrc, bsrc, Wtrg, btrg, Wei, bei,
                               asrc, atrg, aedg, Wproj, Wedge);        // 0
    k2s_scores<<<NN / 32, 256>>>(x);                                   // 1
    kc_convw<<<(FIN * 256 + 255) / 256, 256>>>(Wproj, Wskip);          // 2
    {
        dim3 g2(NN / 64, 4);
        k2_mma<<<g2, 256>>>();                                         // 3 (profiled)
    }
    k0_zero<<<(TWO_N + 255) / 256, 256>>>();                           // 4
    kb_hist<<<(EE + 1023) / 1024, 256>>>(bids);
    kb_scan<<<1, 32>>>();
    kb_fill<<<(EE + 1023) / 1024, 256>>>(bids);
    {
        dim3 g3(38, BB);
        k3_edge<<<g3, 256>>>(edges, ei);
    }
    k4a_scan<<<SNB, SBS>>>();
    k4b_bscan<<<1, 32>>>();
    k4c_add<<<SNB, SBS>>>();
    k5_fill<<<(EE + 255) / 256, 256>>>(ei);
    k6_agg<<<NN / 4, 256>>>(bias, gamma, beta, out);
    (void)out_size;
}

// round 17
// speedup vs baseline: 1.2635x; 1.2635x over previous
#include <cuda_runtime.h>
#include <cuda_bf16.h>
#include <mma.h>

using namespace nvcuda;

// ---------------- problem constants (fixed for this problem) ----------------
#define NN   96000      // nodes
#define EE   600000     // edges
#define HH   4          // heads
#define FFd  32         // features per head
#define HFd  128        // H*F
#define FIN  128        // input features
#define EDd  64         // edge feature dim
#define HID  256        // instruction hidden
#define BB   64         // batch
#define MLEc 1500       // max_local_entity
#define TWO_N (2*NN)
#define SBS  1024
#define SNB  ((TWO_N + SBS - 1) / SBS)   // 188

// k2_mma tiling
#define GR  64          // rows per block
#define GC  128         // cols per block (blockIdx.y in {0,1})
#define SA  136         // smem leading dim (bf16 elems, padded)
#define K2_SMEM ((2 * GR * SA + 2 * FIN * SA) * 2)   // 104448 bytes

// ---------------- device scratch (static: no runtime allocation) -----------
__device__ float g_proj [(size_t)NN * HFd];   // x @ W_proj          49 MB
__device__ float g_skipb[(size_t)NN * HFd];   // x @ W_skip (bias added in k6)
__device__ float g_ssrc [NN * HH];
__device__ float g_strg [NN * HH];
__device__ float g_p    [(size_t)EE * HH];    // exp(leaky(score))   9.6 MB
__device__ int   g_deg  [TWO_N];
__device__ int   g_offs [TWO_N];
__device__ int   g_cur  [TWO_N];
__device__ int   g_bsum [SNB];
__device__ int   g_bscan[SNB];
__device__ int2  g_adj  [2 * EE];             // (neighbor, edge-id) packed
__device__ float g_Msrc [BB * HH * FIN];
__device__ float g_Mtrg [BB * HH * FIN];
__device__ float g_Medge[BB * HH * EDd];
// edge bucketing by batch id
__device__ int   g_bcnt [BB];
__device__ int   g_boff [BB + 1];
__device__ int   g_bcur [BB];
__device__ int   g_perm [EE];
// bf16-split weights for tensor-core GEMM
__device__ __nv_bfloat16 g_wh[FIN * 256];     // [Wproj | Wskip] hi
__device__ __nv_bfloat16 g_wl[FIN * 256];     // [Wproj | Wskip] lo

// ---------------- K0: zero counters -----------------------------------------
__global__ void k0_zero() {
    int i = blockIdx.x * blockDim.x + threadIdx.x;
    if (i < TWO_N) g_deg[i] = 0;
    if (i < BB)    g_bcnt[i] = 0;
}

// ---------------- K1: instruction bridges -> folded score matrices ----------
__global__ void k1_precompute(const float* __restrict__ ins,
                              const float* __restrict__ Wsrc, const float* __restrict__ bsrc,
                              const float* __restrict__ Wtrg, const float* __restrict__ btrg,
                              const float* __restrict__ Wei,  const float* __restrict__ bei,
                              const float* __restrict__ asrc, const float* __restrict__ atrg,
                              const float* __restrict__ aedg,
                              const float* __restrict__ Wproj, const float* __restrict__ Wedge)
{
    __shared__ float csrc[HFd], ctrg[HFd], cedg[HFd];
    int b = blockIdx.x;
    int j = threadIdx.x;                 // 128 threads
    const float* ib = ins + b * HID;
    float s1 = bsrc[j], s2 = btrg[j], s3 = bei[j];
    for (int k = 0; k < HID; ++k) {
        float iv = ib[k];
        s1 += iv * Wsrc[k * HFd + j];
        s2 += iv * Wtrg[k * HFd + j];
        s3 += iv * Wei [k * HFd + j];
    }
    csrc[j] = s1 * asrc[j];
    ctrg[j] = s2 * atrg[j];
    cedg[j] = s3 * aedg[j];
    __syncthreads();

    int d = j;
    for (int h = 0; h < HH; ++h) {
        float m1 = 0.f, m2 = 0.f;
        for (int f = 0; f < FFd; ++f) {
            float wp = Wproj[d * HFd + h * FFd + f];
            m1 += wp * csrc[h * FFd + f];
            m2 += wp * ctrg[h * FFd + f];
        }
        g_Msrc[b * HH * FIN + h * FIN + d] = m1;
        g_Mtrg[b * HH * FIN + h * FIN + d] = m2;
        if (d < EDd) {
            float m3 = 0.f;
            for (int f = 0; f < FFd; ++f)
                m3 += Wedge[d * HFd + h * FFd + f] * cedg[h * FFd + f];
            g_Medge[b * HH * EDd + h * EDd + d] = m3;
        }
    }
}

// ---------------- K2S: node scores via folded matrices -----------------------
__global__ void __launch_bounds__(256) k2s_scores(const float* __restrict__ x) {
    __shared__ float xs[32][129];
    int t = threadIdx.x;
    int n0 = blockIdx.x * 32;
    for (int i = 0; i < 16; ++i) {
        int idx = i * 256 + t;
        xs[idx >> 7][idx & 127] = x[(size_t)(n0 + (idx >> 7)) * FIN + (idx & 127)];
    }
    __syncthreads();

    int node = t & 31;
    int q = t >> 5;                 // warp-uniform
    int h = q & 3;
    int n = n0 + node;
    int b = n / MLEc;
    const float* Mv = ((q < 4) ? g_Msrc : g_Mtrg) + b * HH * FIN + h * FIN;
    float s = 0.f;
    for (int d = 0; d < FIN; ++d) s += xs[node][d] * Mv[d];
    if (q < 4) g_ssrc[n * 4 + h] = s;
    else       g_strg[n * 4 + h] = s;
}

// ---------------- KC: bf16-split conversion of [Wproj|Wskip] -----------------
__global__ void kc_convw(const float* __restrict__ Wp, const float* __restrict__ Ws) {
    int idx = blockIdx.x * 256 + threadIdx.x;   // 0 .. 128*256-1
    if (idx >= FIN * 256) return;
    int r = idx >> 8, c = idx & 255;
    float v = (c < HFd) ? Wp[r * HFd + c] : Ws[r * HFd + (c - HFd)];
    __nv_bfloat16 h = __float2bfloat16_rn(v);
    g_wh[idx] = h;
    g_wl[idx] = __float2bfloat16_rn(v - __bfloat162float(h));
}

// ---------------- K2: tensor-core GEMM (bf16 split, fp32 acc) ----------------
// C[96000 x 256] = x[96000 x 128] @ [Wproj|Wskip][128 x 256]
// block = 64 rows x 128 cols; A staged in smem from fp32 x (hi/lo in regs);
// all fragments loaded from smem (LDSM path).
__global__ void __launch_bounds__(256) k2_mma(const float* __restrict__ x) {
    extern __shared__ __nv_bfloat16 sm[];
    __nv_bfloat16* Ah = sm;                       // [GR][SA]
    __nv_bfloat16* Al = Ah + GR * SA;
    __nv_bfloat16* Bh = Al + GR * SA;             // [FIN][SA]
    __nv_bfloat16* Bl = Bh + FIN * SA;

    int t = threadIdx.x;
    int n0 = blockIdx.x * GR;
    int c0 = blockIdx.y * GC;                     // 0 or 128

    // stage A: 64x128 fp32, coalesced float4 loads; convert hi/lo in regs
    {
        const float4* xv = (const float4*)(x + (size_t)n0 * FIN);
#pragma unroll
        for (int i = 0; i < 8; ++i) {
            int idx = i * 256 + t;                // 2048 float4 total
            int r = idx >> 5;                     // 32 float4 per row
            int c = (idx & 31) * 4;
            float4 v = xv[idx];
            __nv_bfloat16* ah = &Ah[r * SA + c];
            __nv_bfloat16* al = &Al[r * SA + c];
            __nv_bfloat16 h0 = __float2bfloat16_rn(v.x);
            __nv_bfloat16 h1 = __float2bfloat16_rn(v.y);
            __nv_bfloat16 h2 = __float2bfloat16_rn(v.z);
            __nv_bfloat16 h3 = __float2bfloat16_rn(v.w);
            ah[0] = h0; ah[1] = h1; ah[2] = h2; ah[3] = h3;
            al[0] = __float2bfloat16_rn(v.x - __bfloat162float(h0));
            al[1] = __float2bfloat16_rn(v.y - __bfloat162float(h1));
            al[2] = __float2bfloat16_rn(v.z - __bfloat162float(h2));
            al[3] = __float2bfloat16_rn(v.w - __bfloat162float(h3));
        }
    }
    // stage B: 128x128 bf16 (hi+lo), coalesced 8B loads
    {
#pragma unroll
        for (int i = 0; i < 16; ++i) {
            int idx = i * 256 + t;                // 4096 chunks of 4 bf16
            int r = idx >> 5;
            int c = (idx & 31) * 4;
            *(uint2*)&Bh[r * SA + c] = *(const uint2*)&g_wh[r * 256 + c0 + c];
            *(uint2*)&Bl[r * SA + c] = *(const uint2*)&g_wl[r * 256 + c0 + c];
        }
    }
    __syncthreads();

    int w = t >> 5;
    int wr = w >> 1;                 // row tile 0..3 (16 rows each)
    int wcb = (w & 1) * 64;          // col base 0 or 64 (4 tiles of 16)

    wmma::fragment<wmma::accumulator, 16, 16, 16, float> acc[4];
#pragma unroll
    for (int f = 0; f < 4; ++f) wmma::fill_fragment(acc[f], 0.0f);

#pragma unroll
    for (int k = 0; k < FIN / 16; ++k) {
        wmma::fragment<wmma::matrix_a, 16, 16, 16, __nv_bfloat16, wmma::row_major> ah, al;
        wmma::load_matrix_sync(ah, &Ah[(wr * 16) * SA + k * 16], SA);
        wmma::load_matrix_sync(al, &Al[(wr * 16) * SA + k * 16], SA);
#pragma unroll
        for (int f = 0; f < 4; ++f) {
            wmma::fragment<wmma::matrix_b, 16, 16, 16, __nv_bfloat16, wmma::row_major> bh, bl;
            wmma::load_matrix_sync(bh, &Bh[(k * 16) * SA + wcb + f * 16], SA);
            wmma::load_matrix_sync(bl, &Bl[(k * 16) * SA + wcb + f * 16], SA);
            wmma::mma_sync(acc[f], ah, bh, acc[f]);
            wmma::mma_sync(acc[f], ah, bl, acc[f]);
            wmma::mma_sync(acc[f], al, bh, acc[f]);
        }
    }

    float* dst = (blockIdx.y == 0) ? g_proj : g_skipb;
#pragma unroll
    for (int f = 0; f < 4; ++f) {
        wmma::store_matrix_sync(dst + (size_t)(n0 + wr * 16) * HFd + wcb + f * 16,
                                acc[f], HFd, wmma::mem_row_major);
    }
}

// ---------------- KB: bucket edges by batch id -------------------------------
__global__ void __launch_bounds__(256) kb_hist(const int* __restrict__ bids) {
    __shared__ int h[BB];
    int t = threadIdx.x;
    if (t < BB) h[t] = 0;
    __syncthreads();
    int base = blockIdx.x * 1024;
#pragma unroll
    for (int j = 0; j < 4; ++j) {
        int e = base + j * 256 + t;
        if (e < EE) atomicAdd(&h[bids[e]], 1);
    }
    __syncthreads();
    if (t < BB && h[t]) atomicAdd(&g_bcnt[t], h[t]);
}

__global__ void kb_scan() {
    if (threadIdx.x == 0) {
        int s = 0;
        for (int b = 0; b < BB; ++b) {
            g_boff[b] = s; g_bcur[b] = s; s += g_bcnt[b];
        }
        g_boff[BB] = s;
    }
}

__global__ void __launch_bounds__(256) kb_fill(const int* __restrict__ bids) {
    __shared__ int h[BB], base[BB];
    int t = threadIdx.x;
    if (t < BB) h[t] = 0;
    __syncthreads();
    int e0 = blockIdx.x * 1024;
    int eb[4], rk[4];
#pragma unroll
    for (int j = 0; j < 4; ++j) {
        int e = e0 + j * 256 + t;
        if (e < EE) { eb[j] = bids[e]; rk[j] = atomicAdd(&h[eb[j]], 1); }
        else eb[j] = -1;
    }
    __syncthreads();
    if (t < BB && h[t]) base[t] = atomicAdd(&g_bcur[t], h[t]);
    __syncthreads();
#pragma unroll
    for (int j = 0; j < 4; ++j) {
        if (eb[j] >= 0) g_perm[base[eb[j]] + rk[j]] = e0 + j * 256 + t;
    }
}

// ---------------- K3: edge scores (batch-grouped) + exp + degree histogram ---
__global__ void __launch_bounds__(256) k3_edge(const float* __restrict__ edges,
                                               const int* __restrict__ ei)
{
    __shared__ float Me[HH * EDd];      // 1 KB
    int b = blockIdx.y;
    int t = threadIdx.x;
    Me[t] = g_Medge[b * HH * EDd + t];
    __syncthreads();

    int start = g_boff[b], end = g_boff[b + 1];
    const float4* Me4 = (const float4*)Me;

    for (int pos = start + blockIdx.x * 256 + t; pos < end; pos += gridDim.x * 256) {
        int e = g_perm[pos];
        const float4* er = (const float4*)(edges + (size_t)e * EDd);
        float a0 = 0.f, a1 = 0.f, a2 = 0.f, a3 = 0.f;
#pragma unroll
        for (int i = 0; i < 16; ++i) {
            float4 v  = er[i];
            float4 m0 = Me4[i];
            float4 m1 = Me4[16 + i];
            float4 m2 = Me4[32 + i];
            float4 m3 = Me4[48 + i];
            a0 += v.x * m0.x + v.y * m0.y + v.z * m0.z + v.w * m0.w;
            a1 += v.x * m1.x + v.y * m1.y + v.z * m1.z + v.w * m1.w;
            a2 += v.x * m2.x + v.y * m2.y + v.z * m2.z + v.w * m2.w;
            a3 += v.x * m3.x + v.y * m3.y + v.z * m3.z + v.w * m3.w;
        }
        int sv = ei[e], tv = ei[EE + e];
        float4 ss = *(const float4*)&g_ssrc[sv * 4];
        float4 st = *(const float4*)&g_strg[tv * 4];
        float s0 = a0 + ss.x + st.x;
        float s1 = a1 + ss.y + st.y;
        float s2 = a2 + ss.z + st.z;
        float s3 = a3 + ss.w + st.w;
        s0 = (s0 > 0.f) ? s0 : 0.2f * s0;
        s1 = (s1 > 0.f) ? s1 : 0.2f * s1;
        s2 = (s2 > 0.f) ? s2 : 0.2f * s2;
        s3 = (s3 > 0.f) ? s3 : 0.2f * s3;
        float4 p = make_float4(__expf(s0), __expf(s1), __expf(s2), __expf(s3));
        *(float4*)&g_p[(size_t)e * 4] = p;
        atomicAdd(&g_deg[sv], 1);
        atomicAdd(&g_deg[NN + tv], 1);
    }
}

// ---------------- K4: exclusive scan of degrees -> CSR offsets ---------------
__global__ void __launch_bounds__(SBS) k4a_scan() {
    __shared__ int sh[SBS];
    int t = threadIdx.x;
    int i = blockIdx.x * SBS + t;
    int v = (i < TWO_N) ? g_deg[i] : 0;
    sh[t] = v;
    __syncthreads();
    for (int off = 1; off < SBS; off <<= 1) {
        int tmp = (t >= off) ? sh[t - off] : 0;
        __syncthreads();
        if (t >= off) sh[t] += tmp;
        __syncthreads();
    }
    if (i < TWO_N) g_offs[i] = sh[t] - v;
    if (t == SBS - 1) g_bsum[blockIdx.x] = sh[t];
}

__global__ void k4b_bscan() {
    if (threadIdx.x == 0) {
        int s = 0;
        for (int i = 0; i < SNB; ++i) { g_bscan[i] = s; s += g_bsum[i]; }
    }
}

__global__ void __launch_bounds__(SBS) k4c_add() {
    int i = blockIdx.x * SBS + threadIdx.x;
    if (i < TWO_N) {
        int o = g_offs[i] + g_bscan[blockIdx.x];
        g_offs[i] = o;
        g_cur[i]  = o;
    }
}

// ---------------- K5: fill CSR (both directions, int2 packed) ----------------
__global__ void k5_fill(const int* __restrict__ ei) {
    int e = blockIdx.x * blockDim.x + threadIdx.x;
    if (e >= EE) return;
    int s = ei[e], t = ei[EE + e];
    int p1 = atomicAdd(&g_cur[s], 1);
    g_adj[p1] = make_int2(t, e);
    int p2 = atomicAdd(&g_cur[NN + t], 1);
    g_adj[p2] = make_int2(s, e);
}

// ---------------- K6: gather-aggregate + fused LN (1 warp per node) ----------
__global__ void __launch_bounds__(256) k6_agg(const float* __restrict__ bias,
                                              const float* __restrict__ gamma,
                                              const float* __restrict__ beta,
                                              float* __restrict__ out)
{
    int n = (blockIdx.x * 256 + threadIdx.x) >> 5;
    if (n >= NN) return;
    int l = threadIdx.x & 31;
    int h = l >> 3;

    float4 aS = make_float4(0.f, 0.f, 0.f, 0.f); float dS = 0.f;
    {
        int st = g_offs[n], cnt = g_deg[n];
        int2 ne = (cnt > 0) ? g_adj[st] : make_int2(0, 0);
        for (int i = 0; i < cnt; ++i) {
            int2 cur = ne;
            if (i + 1 < cnt) ne = g_adj[st + i + 1];
            float w = g_p[(size_t)cur.y * 4 + h];
            float4 pv = *(const float4*)&g_proj[(size_t)cur.x * HFd + l * 4];
            aS.x += pv.x * w; aS.y += pv.y * w; aS.z += pv.z * w; aS.w += pv.w * w;
            dS += w;
        }
    }
    float4 aT = make_float4(0.f, 0.f, 0.f, 0.f); float dT = 0.f;
    {
        int st = g_offs[NN + n], cnt = g_deg[NN + n];
        int2 ne = (cnt > 0) ? g_adj[st] : make_int2(0, 0);
        for (int i = 0; i < cnt; ++i) {
            int2 cur = ne;
            if (i + 1 < cnt) ne = g_adj[st + i + 1];
            float w = g_p[(size_t)cur.y * 4 + h];
            float4 pv = *(const float4*)&g_proj[(size_t)cur.x * HFd + l * 4];
            aT.x += pv.x * w; aT.y += pv.y * w; aT.z += pv.z * w; aT.w += pv.w * w;
            dT += w;
        }
    }

    float4 sk = *(const float4*)&g_skipb[(size_t)n * HFd + l * 4];
    float4 bi = *(const float4*)&bias[l * 4];
    sk.x += bi.x; sk.y += bi.y; sk.z += bi.z; sk.w += bi.w;
    float iS = (dS > 0.f) ? 1.f / dS : 0.f;
    float iT = (dT > 0.f) ? 1.f / dT : 0.f;
    float4 sv = make_float4(aS.x * iS + sk.x, aS.y * iS + sk.y,
                            aS.z * iS + sk.z, aS.w * iS + sk.w);
    float4 tv = make_float4(aT.x * iT + sk.x, aT.y * iT + sk.y,
                            aT.z * iT + sk.z, aT.w * iT + sk.w);

    float sum = sv.x + sv.y + sv.z + sv.w + tv.x + tv.y + tv.z + tv.w;
    float sq  = sv.x*sv.x + sv.y*sv.y + sv.z*sv.z + sv.w*sv.w
              + tv.x*tv.x + tv.y*tv.y + tv.z*tv.z + tv.w*tv.w;
#pragma unroll
    for (int off = 16; off > 0; off >>= 1) {
        sum += __shfl_xor_sync(0xffffffffu, sum, off);
        sq  += __shfl_xor_sync(0xffffffffu, sq,  off);
    }
    float mu  = sum * (1.f / 256.f);
    float var = sq * (1.f / 256.f) - mu * mu;
    float rs  = rsqrtf(var + 1e-5f);

    float4 g0 = *(const float4*)&gamma[l * 4];
    float4 g1 = *(const float4*)&gamma[128 + l * 4];
    float4 b0 = *(const float4*)&beta[l * 4];
    float4 b1 = *(const float4*)&beta[128 + l * 4];

    float4 o0 = make_float4((sv.x - mu) * rs * g0.x + b0.x,
                            (sv.y - mu) * rs * g0.y + b0.y,
                            (sv.z - mu) * rs * g0.z + b0.z,
                            (sv.w - mu) * rs * g0.w + b0.w);
    float4 o1 = make_float4((tv.x - mu) * rs * g1.x + b1.x,
                            (tv.y - mu) * rs * g1.y + b1.y,
                            (tv.z - mu) * rs * g1.z + b1.z,
                            (tv.w - mu) * rs * g1.w + b1.w);
    *(float4*)&out[(size_t)n * 256 + l * 4]       = o0;
    *(float4*)&out[(size_t)n * 256 + 128 + l * 4] = o1;
}

// ---------------- launch ----------------------------------------------------
extern "C" void kernel_launch(void* const* d_in, const int* in_sizes, int n_in,
                              void* d_out, int out_size)
{
    int o = 0;
    if (n_in >= 21 && in_sizes[5] <= 2) o = 1;

    const float* x     = (const float*)d_in[0];
    const int*   ei    = (const int*)  d_in[1];
    const float* edges = (const float*)d_in[2];
    const float* ins   = (const float*)d_in[3];
    const int*   bids  = (const int*)  d_in[4];
    const float* Wproj = (const float*)d_in[5 + o];
    const float* Wedge = (const float*)d_in[6 + o];
    const float* Wsrc  = (const float*)d_in[7 + o];
    const float* bsrc  = (const float*)d_in[8 + o];
    const float* Wtrg  = (const float*)d_in[9 + o];
    const float* btrg  = (const float*)d_in[10 + o];
    const float* Wei   = (const float*)d_in[11 + o];
    const float* bei   = (const float*)d_in[12 + o];
    const float* asrc  = (const float*)d_in[13 + o];
    const float* atrg  = (const float*)d_in[14 + o];
    const float* aedg  = (const float*)d_in[15 + o];
    const float* bias  = (const float*)d_in[16 + o];
    const float* Wskip = (const float*)d_in[17 + o];
    const float* gamma = (const float*)d_in[18 + o];
    const float* beta  = (const float*)d_in[19 + o];
    float* out = (float*)d_out;

    cudaFuncSetAttribute(k2_mma, cudaFuncAttributeMaxDynamicSharedMemorySize, K2_SMEM);

    // launch index 3 == profiled kernel -> k2_mma
    k1_precompute<<<BB, 128>>>(ins, Wsrc, bsrc, Wtrg, btrg, Wei, bei,
                               asrc, atrg, aedg, Wproj, Wedge);        // 0
    k2s_scores<<<NN / 32, 256>>>(x);                                   // 1
    kc_convw<<<(FIN * 256 + 255) / 256, 256>>>(Wproj, Wskip);          // 2
    {
        dim3 g2(NN / GR, 2);
        k2_mma<<<g2, 256, K2_SMEM>>>(x);                               // 3 (profiled)
    }
    k0_zero<<<(TWO_N + 255) / 256, 256>>>();                           // 4
    kb_hist<<<(EE + 1023) / 1024, 256>>>(bids);
    kb_scan<<<1, 32>>>();
    kb_fill<<<(EE + 1023) / 1024, 256>>>(bids);
    {
        dim3 g3(38, BB);
        k3_edge<<<g3, 256>>>(edges, ei);
    }
    k4a_scan<<<SNB, SBS>>>();
    k4b_bscan<<<1, 32>>>();
    k4c_add<<<SNB, SBS>>>();
    k5_fill<<<(EE + 255) / 256, 256>>>(ei);
    k6_agg<<<(NN * 32) / 256, 256>>>(bias, gamma, beta, out);
    (void)out_size;
}